// round 16
// baseline (speedup 1.0000x reference)
#include <cuda_runtime.h>
#include <cstdint>

// Shapes fixed by the reference
#define BB 16
#define TT 8192
#define CC 512
#define C4 (CC / 4)              // 128 float4 lanes per frame row
#define YY 256
#define NSPAN (BB * YY)          // 4096
#define NPAIR (NSPAN / 2)        // 2048 work items (adjacent span pairs)
#define ROWB (CC * 4)            // 2048 bytes per frame row
#define RPC 32                   // max rows per chunk (64KB stage)
#define STAGES 3
#define NCONS 128                // consumer threads (4 warps)
#define NTHR (NCONS + 32)        // + 1 producer warp
#define GRID_POOL 148            // 1 block/SM

// Steal state (self-restoring each launch; graph-replay safe)
__device__ int g_next = GRID_POOL;
__device__ int g_done = 0;

// ---------------- mbarrier / bulk-copy primitives (R15-proven) ----------------
__device__ __forceinline__ uint32_t sm32(const void* p) {
    return (uint32_t)__cvta_generic_to_shared(p);
}
__device__ __forceinline__ void mbar_init(uint32_t a, uint32_t cnt) {
    asm volatile("mbarrier.init.shared.b64 [%0], %1;" :: "r"(a), "r"(cnt) : "memory");
}
__device__ __forceinline__ void mbar_expect_tx(uint32_t a, uint32_t bytes) {
    asm volatile("mbarrier.arrive.expect_tx.shared.b64 _, [%0], %1;"
                 :: "r"(a), "r"(bytes) : "memory");
}
__device__ __forceinline__ void mbar_arrive(uint32_t a) {
    asm volatile("mbarrier.arrive.shared.b64 _, [%0];" :: "r"(a) : "memory");
}
__device__ __forceinline__ void mbar_wait(uint32_t a, uint32_t parity) {
    uint32_t done;
    asm volatile("{\n\t.reg .pred p;\n\t"
                 "mbarrier.try_wait.parity.acquire.cta.shared::cta.b64 p, [%1], %2;\n\t"
                 "selp.b32 %0, 1, 0, p;\n\t}"
                 : "=r"(done) : "r"(a), "r"(parity) : "memory");
    while (!done) {
        asm volatile("{\n\t.reg .pred p;\n\t"
                     "mbarrier.try_wait.parity.acquire.cta.shared::cta.b64 p, [%1], %2, 0x989680;\n\t"
                     "selp.b32 %0, 1, 0, p;\n\t}"
                     : "=r"(done) : "r"(a), "r"(parity) : "memory");
    }
}
__device__ __forceinline__ void bulk_g2s(uint32_t dst, const void* src,
                                         uint32_t bytes, uint32_t mbar) {
    asm volatile("cp.async.bulk.shared::cta.global.mbarrier::complete_tx::bytes "
                 "[%0], [%1], %2, [%3];"
                 :: "r"(dst), "l"(src), "r"(bytes), "r"(mbar) : "memory");
}

// Accumulate m rows (starting at row offset roff) from a stage buffer lane.
__device__ __forceinline__ void acc_rows(const float4* sp, int roff, int m,
                                         float4& acc) {
    float4 s0 = make_float4(0.f, 0.f, 0.f, 0.f);
    float4 s1 = s0, s2 = s0, s3 = s0;
    int r = 0;
    for (; r + 4 <= m; r += 4) {
        const float4 v0 = sp[(roff + r + 0) * C4];
        const float4 v1 = sp[(roff + r + 1) * C4];
        const float4 v2 = sp[(roff + r + 2) * C4];
        const float4 v3 = sp[(roff + r + 3) * C4];
        s0.x += v0.x; s0.y += v0.y; s0.z += v0.z; s0.w += v0.w;
        s1.x += v1.x; s1.y += v1.y; s1.z += v1.z; s1.w += v1.w;
        s2.x += v2.x; s2.y += v2.y; s2.z += v2.z; s2.w += v2.w;
        s3.x += v3.x; s3.y += v3.y; s3.z += v3.z; s3.w += v3.w;
    }
    for (; r < m; r++) {
        const float4 vv = sp[(roff + r) * C4];
        s0.x += vv.x; s0.y += vv.y; s0.z += vv.z; s0.w += vv.w;
    }
    acc.x += (s0.x + s1.x) + (s2.x + s3.x);
    acc.y += (s0.y + s1.y) + (s2.y + s3.y);
    acc.z += (s0.z + s1.z) + (s2.z + s3.z);
    acc.w += (s0.w + s1.w) + (s2.w + s3.w);
}

// ---------------------------------------------------------------------------
// Warp-specialized persistent kernel: span-PAIR work items, balanced chunks.
// Producer warp: steals pairs (2 adjacent spans = one contiguous byte range),
// computes clipped cums (ce0<=ce1<=ce2), writes zeros for empty spans, and
// streams the pair's R=ce2-ce0 rows as ceil(R/32) BALANCED chunks (no tiny
// tail requests). Chunk geometry depends only on durations -> deterministic.
// Consumer warps: per chunk, split accumulation at the intra-pair boundary
// using per-stage descriptors; store mean when a span's last row arrives.
// acc carries across chunks of the same pair (chunks arrive in order).
// ---------------------------------------------------------------------------
__global__ void __launch_bounds__(NTHR, 1)
pool_pair_kernel(const float* __restrict__ emg,
                 const int*   __restrict__ dur,
                 float*       __restrict__ out) {
    __shared__ alignas(128) float4 buf[STAGES][RPC * C4];   // 192 KB ring
    __shared__ alignas(16)  int4   descA[STAGES];           // {by0, t, rows, ce1}
    __shared__ alignas(16)  int4   descB[STAGES];           // {ce0, ce2, -, -}
    __shared__ alignas(8)   unsigned long long mb_full[STAGES];
    __shared__ alignas(8)   unsigned long long mb_empty[STAGES];

    const int tid = threadIdx.x;

    if (tid == 0) {
        #pragma unroll
        for (int s = 0; s < STAGES; s++) {
            mbar_init(sm32(&mb_full[s]),  1);   // producer arrive (expect_tx) + tx
            mbar_init(sm32(&mb_empty[s]), 4);   // one arrive per consumer warp
        }
    }
    __syncthreads();

    if (tid >= NCONS) {
        // ===================== PRODUCER WARP =====================
        const int lane = tid - NCONS;          // 0..31
        const bool leader = (lane == 0);
        const int4* dur4 = reinterpret_cast<const int4*>(dur);
        int p_stg = 0, p_ph = 1;               // producer cursor (phase starts 1)

        int pr = blockIdx.x;                   // pair index
        while (pr < NPAIR) {
            int nxt = 0;
            if (leader) nxt = atomicAdd(&g_next, 1);   // steal early

            const int b   = pr >> 7;           // 128 pairs per batch
            const int y0  = (pr & 127) * 2;    // first span of pair (even)
            const int by0 = b * YY + y0;

            // metadata: 32 lanes x 8 durations each (L1-resident row)
            const int4 u = __ldg(dur4 + b * 64 + lane * 2);
            const int4 v = __ldg(dur4 + b * 64 + lane * 2 + 1);
            const int base = lane * 8;
            int s = 0;
            if (base + 0 < y0) s += u.x;
            if (base + 1 < y0) s += u.y;
            if (base + 2 < y0) s += u.z;
            if (base + 3 < y0) s += u.w;
            if (base + 4 < y0) s += v.x;
            if (base + 5 < y0) s += v.y;
            if (base + 6 < y0) s += v.z;
            if (base + 7 < y0) s += v.w;
            const int start_raw = __reduce_add_sync(0xffffffffu, s);
            // the pair's two durations live in lane y0>>3 (y0 even)
            const int p = y0 & 7;              // 0,2,4,6
            const int d0l = (p == 0) ? u.x : (p == 2) ? u.z : (p == 4) ? v.x : v.z;
            const int d1l = (p == 0) ? u.y : (p == 2) ? u.w : (p == 4) ? v.y : v.w;
            const int d0 = __shfl_sync(0xffffffffu, d0l, y0 >> 3);
            const int d1 = __shfl_sync(0xffffffffu, d1l, y0 >> 3);

            const int ce0 = min(start_raw, TT);
            const int ce1 = min(start_raw + d0, TT);
            const int ce2 = min(start_raw + d0 + d1, TT);

            // zero-writes for empty spans (all 32 lanes cooperate)
            const float4 z = make_float4(0.f, 0.f, 0.f, 0.f);
            if (ce1 == ce0) {
                float4* o = reinterpret_cast<float4*>(out) + (size_t)by0 * C4;
                o[lane] = z; o[lane + 32] = z; o[lane + 64] = z; o[lane + 96] = z;
            }
            if (ce2 == ce1) {
                float4* o = reinterpret_cast<float4*>(out) + (size_t)(by0 + 1) * C4;
                o[lane] = z; o[lane + 32] = z; o[lane + 64] = z; o[lane + 96] = z;
            }

            const int R = ce2 - ce0;
            if (leader && R > 0) {
                const int nch  = (R + RPC - 1) / RPC;
                const int bsz  = R / nch;
                const int rem  = R % nch;
                const char* src = reinterpret_cast<const char*>(emg)
                                  + ((size_t)b * TT + ce0) * ROWB;
                int off = 0;
                for (int c = 0; c < nch; c++) {
                    const int rows = bsz + (c < rem ? 1 : 0);
                    mbar_wait(sm32(&mb_empty[p_stg]), p_ph);
                    descA[p_stg] = make_int4(by0, ce0 + off, rows, ce1);
                    descB[p_stg] = make_int4(ce0, ce2, 0, 0);
                    mbar_expect_tx(sm32(&mb_full[p_stg]), rows * ROWB);
                    bulk_g2s(sm32(&buf[p_stg][0]), src + (size_t)off * ROWB,
                             rows * ROWB, sm32(&mb_full[p_stg]));
                    off += rows;
                    if (++p_stg == STAGES) { p_stg = 0; p_ph ^= 1; }
                }
            }
            pr = __shfl_sync(0xffffffffu, nxt, 0);
        }

        // terminal descriptor (dummy 16B copy satisfies the tx count)
        if (leader) {
            mbar_wait(sm32(&mb_empty[p_stg]), p_ph);
            descA[p_stg] = make_int4(-1, 0, 0, 0);
            mbar_expect_tx(sm32(&mb_full[p_stg]), 16);
            bulk_g2s(sm32(&buf[p_stg][0]), emg, 16, sm32(&mb_full[p_stg]));
        }
    } else {
        // ===================== CONSUMER WARPS =====================
        int c_stg = 0, c_ph = 0;               // consumer cursor (phase starts 0)
        float4 acc = make_float4(0.f, 0.f, 0.f, 0.f);
        for (;;) {
            mbar_wait(sm32(&mb_full[c_stg]), c_ph);
            const int4 dA = descA[c_stg];      // broadcast LDS
            if (dA.x < 0) break;               // terminal
            const int4 dB = descB[c_stg];
            const int by0 = dA.x;
            int       t   = dA.y;              // chunk start (absolute frame)
            const int n   = dA.z;
            const int ce1 = dA.w;
            const int ce0 = dB.x;
            const int ce2 = dB.y;
            const int chunk_end = t + n;
            const float4* sp = &buf[c_stg][tid];
            int roff = 0;

            // span 0 segment
            if (t < ce1) {
                const int e = min(ce1, chunk_end);
                acc_rows(sp, roff, e - t, acc);
                roff += e - t;
                if (e == ce1) {                // span 0 completes here
                    const float inv = 1.0f / (float)(ce1 - ce0);
                    float4 r;
                    r.x = acc.x * inv; r.y = acc.y * inv;
                    r.z = acc.z * inv; r.w = acc.w * inv;
                    reinterpret_cast<float4*>(out)[(size_t)by0 * C4 + tid] = r;
                    acc = make_float4(0.f, 0.f, 0.f, 0.f);
                }
                t = e;
            }
            // span 1 segment
            if (t < ce2 && t < chunk_end) {
                const int e = min(ce2, chunk_end);
                acc_rows(sp, roff, e - t, acc);
                if (e == ce2) {                // span 1 completes here
                    const float inv = 1.0f / (float)(ce2 - ce1);
                    float4 r;
                    r.x = acc.x * inv; r.y = acc.y * inv;
                    r.z = acc.z * inv; r.w = acc.w * inv;
                    reinterpret_cast<float4*>(out)[(size_t)(by0 + 1) * C4 + tid] = r;
                    acc = make_float4(0.f, 0.f, 0.f, 0.f);
                }
            }

            __syncwarp();
            if ((tid & 31) == 0) mbar_arrive(sm32(&mb_empty[c_stg]));
            if (++c_stg == STAGES) { c_stg = 0; c_ph ^= 1; }
        }
    }

    // last block restores steal state for the next (graph) replay
    __syncthreads();
    if (tid == 0) {
        const int dd = atomicAdd(&g_done, 1);
        if (dd == GRID_POOL - 1) {
            g_next = GRID_POOL;
            g_done = 0;
            __threadfence();
        }
    }
}

extern "C" void kernel_launch(void* const* d_in, const int* in_sizes, int n_in,
                              void* d_out, int out_size) {
    const float* emg = (const float*)d_in[0];
    const int*   dur = (const int*)d_in[1];
    float*       out = (float*)d_out;

    pool_pair_kernel<<<GRID_POOL, NTHR>>>(emg, dur, out);
}

// round 17
// speedup vs baseline: 1.1038x; 1.1038x over previous
#include <cuda_runtime.h>
#include <cstdint>

// Shapes fixed by the reference
#define BB 16
#define TT 8192
#define CC 512
#define C4 (CC / 4)              // 128 float4 lanes per frame row
#define YY 256
#define NSPAN (BB * YY)          // 4096
#define ROWB (CC * 4)            // 2048 bytes per frame row
#define RPC 32                   // max rows per chunk (64KB stage)
#define STAGES 3
#define NCONS 128                // consumer threads (4 warps)
#define NTHR (NCONS + 32)        // + 1 producer warp
#define GRID_POOL 148            // 1 block/SM

// Steal state (self-restoring each launch; graph-replay safe)
__device__ int g_next = GRID_POOL;
__device__ int g_done = 0;

// ---------------- mbarrier / bulk-copy primitives (R15-proven) ----------------
__device__ __forceinline__ uint32_t sm32(const void* p) {
    return (uint32_t)__cvta_generic_to_shared(p);
}
__device__ __forceinline__ void mbar_init(uint32_t a, uint32_t cnt) {
    asm volatile("mbarrier.init.shared.b64 [%0], %1;" :: "r"(a), "r"(cnt) : "memory");
}
__device__ __forceinline__ void mbar_expect_tx(uint32_t a, uint32_t bytes) {
    asm volatile("mbarrier.arrive.expect_tx.shared.b64 _, [%0], %1;"
                 :: "r"(a), "r"(bytes) : "memory");
}
__device__ __forceinline__ void mbar_arrive(uint32_t a) {
    asm volatile("mbarrier.arrive.shared.b64 _, [%0];" :: "r"(a) : "memory");
}
__device__ __forceinline__ void mbar_wait(uint32_t a, uint32_t parity) {
    uint32_t done;
    asm volatile("{\n\t.reg .pred p;\n\t"
                 "mbarrier.try_wait.parity.acquire.cta.shared::cta.b64 p, [%1], %2;\n\t"
                 "selp.b32 %0, 1, 0, p;\n\t}"
                 : "=r"(done) : "r"(a), "r"(parity) : "memory");
    while (!done) {
        asm volatile("{\n\t.reg .pred p;\n\t"
                     "mbarrier.try_wait.parity.acquire.cta.shared::cta.b64 p, [%1], %2, 0x989680;\n\t"
                     "selp.b32 %0, 1, 0, p;\n\t}"
                     : "=r"(done) : "r"(a), "r"(parity) : "memory");
    }
}
__device__ __forceinline__ void bulk_g2s(uint32_t dst, const void* src,
                                         uint32_t bytes, uint32_t mbar) {
    asm volatile("cp.async.bulk.shared::cta.global.mbarrier::complete_tx::bytes "
                 "[%0], [%1], %2, [%3];"
                 :: "r"(dst), "l"(src), "r"(bytes), "r"(mbar) : "memory");
}

// ---------------------------------------------------------------------------
// Warp-specialized persistent kernel = R15 (64KB ring, 1 block/SM, 3 stages)
// with ONE producer-side change: spans needing 2 chunks get BALANCED splits
// (17+16 instead of 32+1), raising the minimum DRAM request from 2KB to
// ~32KB. Consumer protocol identical; row loop generalized to unroll-4 +
// tail for any n (branch-light). Chunk geometry depends only on durations
// -> bitwise deterministic.
// ---------------------------------------------------------------------------
__global__ void __launch_bounds__(NTHR, 1)
pool_tma_kernel(const float* __restrict__ emg,
                const int*   __restrict__ dur,
                float*       __restrict__ out) {
    __shared__ alignas(128) float4 buf[STAGES][RPC * C4];   // 192 KB ring
    __shared__ alignas(16)  int4   desc[STAGES];            // {by, rows, inv, last}
    __shared__ alignas(8)   unsigned long long mb_full[STAGES];
    __shared__ alignas(8)   unsigned long long mb_empty[STAGES];

    const int tid = threadIdx.x;

    if (tid == 0) {
        #pragma unroll
        for (int s = 0; s < STAGES; s++) {
            mbar_init(sm32(&mb_full[s]),  1);   // producer arrive (expect_tx) + tx
            mbar_init(sm32(&mb_empty[s]), 4);   // one arrive per consumer warp
        }
    }
    __syncthreads();

    if (tid >= NCONS) {
        // ===================== PRODUCER WARP =====================
        const int lane = tid - NCONS;          // 0..31
        const bool leader = (lane == 0);
        const int4* dur4 = reinterpret_cast<const int4*>(dur);
        int p_stg = 0, p_ph = 1;               // producer cursor (phase starts 1)

        int by = blockIdx.x;
        while (by < NSPAN) {
            int nxt = 0;
            if (leader) nxt = atomicAdd(&g_next, 1);   // steal early

            const int b = by >> 8;             // YY == 256
            const int y = by & 255;

            // metadata: 32 lanes x 8 durations each
            const int4 u = __ldg(dur4 + b * 64 + lane * 2);
            const int4 v = __ldg(dur4 + b * 64 + lane * 2 + 1);
            const int base = lane * 8;
            int s = 0;
            if (base + 0 < y) s += u.x;
            if (base + 1 < y) s += u.y;
            if (base + 2 < y) s += u.z;
            if (base + 3 < y) s += u.w;
            if (base + 4 < y) s += v.x;
            if (base + 5 < y) s += v.y;
            if (base + 6 < y) s += v.z;
            if (base + 7 < y) s += v.w;
            int c_lane = 0;
            if ((y >> 3) == lane) {
                switch (y & 7) {
                    case 0:  c_lane = u.x; break;
                    case 1:  c_lane = u.y; break;
                    case 2:  c_lane = u.z; break;
                    case 3:  c_lane = u.w; break;
                    case 4:  c_lane = v.x; break;
                    case 5:  c_lane = v.y; break;
                    case 6:  c_lane = v.z; break;
                    default: c_lane = v.w; break;
                }
            }
            const int start_raw = __reduce_add_sync(0xffffffffu, s);
            const int dcnt = __shfl_sync(0xffffffffu, c_lane, y >> 3);
            const int st  = min(start_raw, TT);
            const int en  = min(start_raw + dcnt, TT);
            const int cnt = en - st;

            if (cnt == 0) {
                // empty span: producer writes the zeros itself
                const float4 z = make_float4(0.f, 0.f, 0.f, 0.f);
                float4* o = reinterpret_cast<float4*>(out) + (size_t)by * C4;
                o[lane]      = z;
                o[lane + 32] = z;
                o[lane + 64] = z;
                o[lane + 96] = z;
            } else if (leader) {
                const char* src = reinterpret_cast<const char*>(emg)
                                  + ((size_t)b * TT + st) * ROWB;
                const float inv = 1.0f / (float)cnt;
                const int nch = (cnt + RPC - 1) / RPC;       // 1 or 2
                const int bsz = cnt / nch;
                const int rem = cnt % nch;
                int off = 0;
                for (int c = 0; c < nch; c++) {
                    const int rows = bsz + (c < rem ? 1 : 0); // balanced split
                    mbar_wait(sm32(&mb_empty[p_stg]), p_ph);
                    desc[p_stg] = make_int4(by, rows, __float_as_int(inv),
                                            (c == nch - 1) ? 1 : 0);
                    mbar_expect_tx(sm32(&mb_full[p_stg]), rows * ROWB);
                    bulk_g2s(sm32(&buf[p_stg][0]), src + (size_t)off * ROWB,
                             rows * ROWB, sm32(&mb_full[p_stg]));
                    off += rows;
                    if (++p_stg == STAGES) { p_stg = 0; p_ph ^= 1; }
                }
            }
            by = __shfl_sync(0xffffffffu, nxt, 0);
        }

        // terminal descriptor (dummy 16B copy satisfies the tx count)
        if (leader) {
            mbar_wait(sm32(&mb_empty[p_stg]), p_ph);
            desc[p_stg] = make_int4(-1, 0, 0, 0);
            mbar_expect_tx(sm32(&mb_full[p_stg]), 16);
            bulk_g2s(sm32(&buf[p_stg][0]), emg, 16, sm32(&mb_full[p_stg]));
        }
    } else {
        // ===================== CONSUMER WARPS =====================
        int c_stg = 0, c_ph = 0;               // consumer cursor (phase starts 0)
        float4 acc = make_float4(0.f, 0.f, 0.f, 0.f);
        for (;;) {
            mbar_wait(sm32(&mb_full[c_stg]), c_ph);
            const int4 d = desc[c_stg];        // broadcast LDS
            if (d.x < 0) break;                // terminal

            const float4* sp = &buf[c_stg][tid];
            const int n = d.y;
            // generic unroll-4 + tail (branch-light; n in [1,32])
            float4 s0 = make_float4(0.f, 0.f, 0.f, 0.f);
            float4 s1 = s0, s2 = s0, s3 = s0;
            int r = 0;
            for (; r + 4 <= n; r += 4) {
                const float4 v0 = sp[(r + 0) * C4];
                const float4 v1 = sp[(r + 1) * C4];
                const float4 v2 = sp[(r + 2) * C4];
                const float4 v3 = sp[(r + 3) * C4];
                s0.x += v0.x; s0.y += v0.y; s0.z += v0.z; s0.w += v0.w;
                s1.x += v1.x; s1.y += v1.y; s1.z += v1.z; s1.w += v1.w;
                s2.x += v2.x; s2.y += v2.y; s2.z += v2.z; s2.w += v2.w;
                s3.x += v3.x; s3.y += v3.y; s3.z += v3.z; s3.w += v3.w;
            }
            for (; r < n; r++) {
                const float4 vv = sp[r * C4];
                s0.x += vv.x; s0.y += vv.y; s0.z += vv.z; s0.w += vv.w;
            }
            acc.x += (s0.x + s1.x) + (s2.x + s3.x);
            acc.y += (s0.y + s1.y) + (s2.y + s3.y);
            acc.z += (s0.z + s1.z) + (s2.z + s3.z);
            acc.w += (s0.w + s1.w) + (s2.w + s3.w);

            if (d.w) {                         // last chunk of span
                const float inv = __int_as_float(d.z);
                float4 rr;
                rr.x = acc.x * inv; rr.y = acc.y * inv;
                rr.z = acc.z * inv; rr.w = acc.w * inv;
                reinterpret_cast<float4*>(out)[(size_t)d.x * C4 + tid] = rr;
                acc = make_float4(0.f, 0.f, 0.f, 0.f);
            }

            __syncwarp();
            if ((tid & 31) == 0) mbar_arrive(sm32(&mb_empty[c_stg]));
            if (++c_stg == STAGES) { c_stg = 0; c_ph ^= 1; }
        }
    }

    // last block restores steal state for the next (graph) replay
    __syncthreads();
    if (tid == 0) {
        const int dd = atomicAdd(&g_done, 1);
        if (dd == GRID_POOL - 1) {
            g_next = GRID_POOL;
            g_done = 0;
            __threadfence();
        }
    }
}

extern "C" void kernel_launch(void* const* d_in, const int* in_sizes, int n_in,
                              void* d_out, int out_size) {
    const float* emg = (const float*)d_in[0];
    const int*   dur = (const int*)d_in[1];
    float*       out = (float*)d_out;

    pool_tma_kernel<<<GRID_POOL, NTHR>>>(emg, dur, out);
}